// round 11
// baseline (speedup 1.0000x reference)
#include <cuda_runtime.h>

// Problem constants (from reference: B=2048, N=60, C=128)
#define BCOL 2048
#define NL   60
#define CCH  128
#define BLOCK 128

// dynamic smem: THREE per-thread arrays of NL floats, [layer][thread]:
//   arrS: rs[] (phase A) -> overwritten by s_up[] (phase B), read in C
//   arrM: amu[] (phase B) -> read in C
//   arrT: td[]  (phase B) -> read in C
// 90 KB/block -> 2 blocks/SM (8 warps). The small concurrent working set
// makes all phase-to-phase gmem reuse L2-resident.
#define SMEM_FLOATS (3 * NL * BLOCK)
#define SMEM_BYTES  (SMEM_FLOATS * sizeof(float))

__device__ __forceinline__ float frcp(float x) {
    return __fdividef(1.0f, x);     // MUFU.RCP path, ~2ulp
}

struct BufA { float rv[4], tv[4]; };
struct BufB { float sv[4], rv[4], tv[4], av[4]; };
struct BufC { float abv[4]; };

struct BState { float s_prev, r_prev, ds_prev, rt_run, F; };

// ---- load helpers: issue all batch loads back-to-back (max MLP) ----
__device__ __forceinline__ void loadA(BufA& B, const float* __restrict__ r,
                                      const float* __restrict__ t,
                                      unsigned base, int l0) {
    #pragma unroll
    for (int k = 0; k < 4; ++k) {
        unsigned idx = base + (unsigned)(l0 - k) * CCH;
        B.rv[k] = r[idx];
        B.tv[k] = t[idx];
    }
}
__device__ __forceinline__ void loadB(BufB& B, const float* __restrict__ s,
                                      const float* __restrict__ r,
                                      const float* __restrict__ t,
                                      const float* __restrict__ a,
                                      unsigned base, int l0) {
    #pragma unroll
    for (int k = 0; k < 4; ++k) {
        unsigned idx = base + (unsigned)(l0 + k) * CCH;
        B.sv[k] = s[idx];
        B.rv[k] = r[idx];
        B.tv[k] = t[idx];
        B.av[k] = a[idx];
    }
}
// absorbed_down: MUST issue after phase B wrote ab for these layers
__device__ __forceinline__ void loadCab(BufC& B, const float* __restrict__ ab,
                                        unsigned base, int m0) {
    #pragma unroll
    for (int k = 0; k < 4; ++k) {
        unsigned idx = base + (unsigned)(m0 - 1 - k) * CCH;
        B.abv[k] = __ldcs(&ab[idx]);  // read once, then overwritten
    }
}

// ---- compute helpers ----
__device__ __forceinline__ float compA(float rs_run, const BufA& B, int l0,
                                       float* sh, int tx) {
    #pragma unroll
    for (int k = 0; k < 4; ++k) {
        float dd = frcp(1.0f - rs_run * B.rv[k]);
        rs_run = B.rv[k] + rs_run * B.tv[k] * B.tv[k] * dd;
        sh[(l0 - k) * BLOCK + tx] = rs_run;     // rs[] into arrS
    }
    return rs_run;
}

// Phase B: down flux + absorbed_down (gmem) AND phase-C precompute (smem).
// At layer l, rt_run (pre-update) == rt[l-1] and dd == dt[l], so
//   s_up[l] = dt[l]*(s[l] + s[l-1]*r[l])
//   amu[l]  = a[l]*(1 + t[l]*rt[l-1]*dt[l])
//   td[l]   = t[l]*dt[l]
__device__ __forceinline__ void compB(BState& st, const BufB& Bu, int l0,
                                      float* sh, int tx, unsigned base,
                                      float* fd, float* ab) {
    float rsv[4];
    #pragma unroll
    for (int k = 0; k < 4; ++k)
        rsv[k] = sh[(l0 + k + 1) * BLOCK + tx];   // rs[l+1], read pre-overwrite
    #pragma unroll
    for (int k = 0; k < 4; ++k) {
        const int l = l0 + k;
        unsigned idx = base + (unsigned)l * CCH;

        // down flux
        float s_down = st.ds_prev * (st.s_prev + Bu.sv[k] * st.r_prev);
        float G = st.F + s_down;
        __stcs(&fd[idx], G);

        float dsl = frcp(1.0f - rsv[k] * Bu.rv[k]);    // ds[l]
        float tdd = Bu.tv[k] * dsl;
        ab[idx] = Bu.av[k] * (1.0f + rsv[k] * tdd) * G; // absorbed_down[l]
        st.F = G * tdd;
        st.ds_prev = dsl;

        // up-direction precompute + rt recurrence
        float dd = frcp(1.0f - st.rt_run * Bu.rv[k]);   // dt[l]
        sh[l * BLOCK + tx] = dd * (Bu.sv[k] + st.s_prev * Bu.rv[k]); // s_up[l]
        sh[(NL * BLOCK) + l * BLOCK + tx] =
            Bu.av[k] * (1.0f + Bu.tv[k] * st.rt_run * dd);           // amu[l]
        sh[(2 * NL * BLOCK) + l * BLOCK + tx] = Bu.tv[k] * dd;       // td[l]
        st.rt_run = Bu.rv[k] + st.rt_run * Bu.tv[k] * Bu.tv[k] * dd;

        st.s_prev = Bu.sv[k];
        st.r_prev = Bu.rv[k];
    }
}

// Phase C: pure smem + ab RMW; 2-FMA chain per layer
__device__ __forceinline__ void compC(float& Fu, const BufC& Bu, int m0,
                                      float* sh, int tx, unsigned base,
                                      float* fu, float* ab) {
    float su[4], am[4], tdv[4];
    #pragma unroll
    for (int k = 0; k < 4; ++k) {
        su[k]  = sh[(m0 - k) * BLOCK + tx];                      // s_up[m]
        am[k]  = sh[(NL * BLOCK) + (m0 - 1 - k) * BLOCK + tx];   // amu[m-1]
        tdv[k] = sh[(2 * NL * BLOCK) + (m0 - 1 - k) * BLOCK + tx]; // td[m-1]
    }
    #pragma unroll
    for (int k = 0; k < 4; ++k) {
        int mm = m0 - k;
        float G = Fu + su[k];
        __stcs(&fu[base + (unsigned)mm * CCH], G);
        __stcs(&ab[base + (unsigned)(mm - 1) * CCH], Bu.abv[k] + G * am[k]);
        Fu = G * tdv[k];
    }
}

__global__ __launch_bounds__(BLOCK, 2)   // 2 blocks/SM (smem-bound anyway)
void adding_doubling_kernel(const float* __restrict__ a,
                            const float* __restrict__ r,
                            const float* __restrict__ t,
                            const float* __restrict__ s,
                            float* __restrict__ out)
{
    extern __shared__ float smem[];
    const int tx = threadIdx.x;

    const unsigned tid = blockIdx.x * BLOCK + tx;
    const unsigned base = (tid >> 7) * (NL * CCH) + (tid & (CCH - 1));
    const unsigned BNC  = BCOL * NL * CCH;

    float* fd = out;            // flux_down
    float* fu = out + BNC;      // flux_up
    float* ab = out + 2u * BNC; // absorbed

#define SM_S(l) smem[(l) * BLOCK + tx]
#define SM_M(l) smem[(NL * BLOCK) + (l) * BLOCK + tx]
#define SM_T(l) smem[(2 * NL * BLOCK) + (l) * BLOCK + tx]

    BufB B0, B1;   // phase-B buffers (B0 pre-loaded during phase A tail)

    // ---------------- Phase A: bottom-up cumulative surface reflection ----
    // ROLLED pipeline: batches l0 = 58,54,...,6 (l=58..3), tail l=2,1
    {
        float rs_run = r[base + (NL - 1) * CCH];
        SM_S(NL - 1) = rs_run;

        BufA A0, A1;
        int l = NL - 2;                       // 58
        loadA(A0, r, t, base, l);
        #pragma unroll 1
        for (int it = 0; it < 6; ++it, l -= 8) {
            loadA(A1, r, t, base, l - 4);
            rs_run = compA(rs_run, A0, l, smem, tx);
            loadA(A0, r, t, base, l - 8);
            rs_run = compA(rs_run, A1, l - 4, smem, tx);
        }
        // l == 10; A0 holds batch 10
        loadA(A1, r, t, base, 6);
        rs_run = compA(rs_run, A0, 10, smem, tx);
        loadB(B0, s, r, t, a, base, 1);       // hide phase-B cold start
        rs_run = compA(rs_run, A1, 6, smem, tx);

        #pragma unroll
        for (int l2 = 2; l2 >= 1; --l2) {     // tail
            unsigned idx = base + (unsigned)l2 * CCH;
            float rl = r[idx], tl = t[idx];
            float dd = frcp(1.0f - rs_run * rl);
            rs_run = rl + rs_run * tl * tl * dd;
            SM_S(l2) = rs_run;
        }
    }

    // ---------------- Phase B: forward — down flux + C-precompute ---------
    // ROLLED pipeline: batches l0 = 1,5,...,53 (l=1..56), tail l=57..59
    {
        BState st;
        st.s_prev = s[base];
        st.r_prev = r[base];
        float rs1 = SM_S(1);
        st.ds_prev = frcp(1.0f - rs1 * st.r_prev);   // ds[0]
        st.rt_run = st.r_prev;                        // rt[0] = r[0]
        __stcs(&fd[base], 0.0f);
        st.F = 0.0f;

        int l = 1;
        #pragma unroll 1
        for (int it = 0; it < 6; ++it, l += 8) {
            loadB(B1, s, r, t, a, base, l + 4);
            compB(st, B0, l, smem, tx, base, fd, ab);
            loadB(B0, s, r, t, a, base, l + 8);
            compB(st, B1, l + 4, smem, tx, base, fd, ab);
        }
        // l == 49; B0 holds batch 49
        loadB(B1, s, r, t, a, base, 53);
        compB(st, B0, 49, smem, tx, base, fd, ab);
        compB(st, B1, 53, smem, tx, base, fd, ab);

        #pragma unroll
        for (int l2 = 57; l2 < NL; ++l2) {    // tail l = 57, 58, 59
            unsigned idx = base + (unsigned)l2 * CCH;
            float sl = s[idx], rl = r[idx], tl = t[idx], al = a[idx];

            float s_down = st.ds_prev * (st.s_prev + sl * st.r_prev);
            float G = st.F + s_down;
            __stcs(&fd[idx], G);

            float absd;
            if (l2 < NL - 1) {
                float rsl1 = SM_S(l2 + 1);
                float dsl  = frcp(1.0f - rsl1 * rl);
                float tdd = tl * dsl;
                absd = al * (1.0f + rsl1 * tdd) * G;
                st.F = G * tdd;
                st.ds_prev = dsl;
            } else {
                absd = al * G;
            }
            ab[idx] = absd;

            // up-direction precompute + rt recurrence
            float dd = frcp(1.0f - st.rt_run * rl);       // dt[l]
            SM_S(l2) = dd * (sl + st.s_prev * rl);        // s_up[l]
            SM_M(l2) = al * (1.0f + tl * st.rt_run * dd); // amu[l]
            SM_T(l2) = tl * dd;                           // td[l]
            st.rt_run = rl + st.rt_run * tl * tl * dd;

            st.s_prev = sl;
            st.r_prev = rl;
        }
    }

    // ---------------- Phase C: reverse — up flux (smem-driven) -------------
    // ROLLED pipeline: batches m0 = 59,55,...,7 (m=59..4), tail m=3,2, epi.
    {
        BufC C0, C1;
        // ab[55..58] written by this same thread in phase B -> L1/L2 hits
        loadCab(C0, ab, base, 59);

        float Fu = 0.0f;
        int m = NL - 1;                        // 59
        #pragma unroll 1
        for (int it = 0; it < 6; ++it, m -= 8) {
            loadCab(C1, ab, base, m - 4);
            compC(Fu, C0, m, smem, tx, base, fu, ab);
            loadCab(C0, ab, base, m - 8);
            compC(Fu, C1, m - 4, smem, tx, base, fu, ab);
        }
        // m == 11; C0 holds batch 11
        loadCab(C1, ab, base, 7);
        compC(Fu, C0, 11, smem, tx, base, fu, ab);
        compC(Fu, C1, 7, smem, tx, base, fu, ab);

        #pragma unroll
        for (int m2 = 3; m2 >= 2; --m2) {      // tail m = 3, 2
            unsigned idxm1 = base + (unsigned)(m2 - 1) * CCH;
            float ab_old = __ldcs(&ab[idxm1]);
            float G = Fu + SM_S(m2);
            __stcs(&fu[base + (unsigned)m2 * CCH], G);
            __stcs(&ab[idxm1], ab_old + G * SM_M(m2 - 1));
            Fu = G * SM_T(m2 - 1);
        }

        // m = 1 and m = 0 epilogue
        float s0 = __ldcs(&s[base]);
        float t0 = __ldcs(&t[base]);
        float a0 = __ldcs(&a[base]);
        float flux1 = Fu + SM_S(1);               // s_up[1]
        __stcs(&fu[base + CCH], flux1);           // flux_up[1]
        __stcs(&ab[base], flux1 * a0);            // absorbed[0] (down = 0)
        __stcs(&fu[base], flux1 * t0 + s0);       // flux_up[0] (s_up[0]=s[0])
    }

#undef SM_S
#undef SM_M
#undef SM_T
}

extern "C" void kernel_launch(void* const* d_in, const int* in_sizes, int n_in,
                              void* d_out, int out_size)
{
    const float* a = (const float*)d_in[0];
    const float* r = (const float*)d_in[1];
    const float* t = (const float*)d_in[2];
    const float* s = (const float*)d_in[3];
    float* out = (float*)d_out;

    cudaFuncSetAttribute(adding_doubling_kernel,
                         cudaFuncAttributeMaxDynamicSharedMemorySize,
                         (int)SMEM_BYTES);

    const int total = BCOL * CCH;                 // 262144 threads
    const int grid = (total + BLOCK - 1) / BLOCK; // 2048 blocks
    adding_doubling_kernel<<<grid, BLOCK, SMEM_BYTES>>>(a, r, t, s, out);
}

// round 12
// speedup vs baseline: 1.4015x; 1.4015x over previous
#include <cuda_runtime.h>

// Problem constants (from reference: B=2048, N=60, C=128)
#define BCOL 2048
#define NL   60
#define CCH  128
#define BLOCK 128

// dynamic smem: ONE per-thread array of NL floats, [layer][thread].
// Holds rs[] (phase A), progressively overwritten by rt[] (phase B).
// Padded to 36 KB (L2 working-set control; regs bind at 5 blocks anyway).
#define SMEM_FLOATS (NL * BLOCK)
#define SMEM_BYTES  (36 * 1024)

__device__ __forceinline__ float frcp(float x) {
    return __fdividef(1.0f, x);     // MUFU.RCP path, ~2ulp
}

struct BufA { float rv[4], tv[4]; };
struct BufB { float sv[4], rv[4], tv[4], av[4]; };
struct BufC { float sv[4], rv[4], tv[4], av[4], abv[4]; };

struct BState { float s_prev, r_prev, ds_prev, rt_run, F; };
struct CState { float Fu, s_m, r_m, dt_m; };

// ---- load helpers: issue all batch loads back-to-back (max MLP) ----
__device__ __forceinline__ void loadA(BufA& B, const float* __restrict__ r,
                                      const float* __restrict__ t,
                                      unsigned base, int l0) {
    #pragma unroll
    for (int k = 0; k < 4; ++k) {
        unsigned idx = base + (unsigned)(l0 - k) * CCH;
        B.rv[k] = r[idx];
        B.tv[k] = t[idx];
    }
}
__device__ __forceinline__ void loadB(BufB& B, const float* __restrict__ s,
                                      const float* __restrict__ r,
                                      const float* __restrict__ t,
                                      const float* __restrict__ a,
                                      unsigned base, int l0) {
    #pragma unroll
    for (int k = 0; k < 4; ++k) {
        unsigned idx = base + (unsigned)(l0 + k) * CCH;
        B.sv[k] = s[idx];
        B.rv[k] = r[idx];
        B.tv[k] = t[idx];
        B.av[k] = a[idx];
    }
}
// pure-input part of a phase-C batch: SAFE to hoist before phase-B writes
__device__ __forceinline__ void loadCin(BufC& B, const float* __restrict__ s,
                                        const float* __restrict__ r,
                                        const float* __restrict__ t,
                                        const float* __restrict__ a,
                                        unsigned base, int m0) {
    #pragma unroll
    for (int k = 0; k < 4; ++k) {
        unsigned idx = base + (unsigned)(m0 - 1 - k) * CCH;
        B.sv[k]  = __ldcs(&s[idx]);   // last use of inputs
        B.rv[k]  = __ldcs(&r[idx]);
        B.tv[k]  = __ldcs(&t[idx]);
        B.av[k]  = __ldcs(&a[idx]);
    }
}
// absorbed_down part: MUST issue after phase B wrote ab for these layers
__device__ __forceinline__ void loadCab(BufC& B, const float* __restrict__ ab,
                                        unsigned base, int m0) {
    #pragma unroll
    for (int k = 0; k < 4; ++k) {
        unsigned idx = base + (unsigned)(m0 - 1 - k) * CCH;
        B.abv[k] = __ldcs(&ab[idx]);  // read once, then overwritten
    }
}
__device__ __forceinline__ void loadC(BufC& B, const float* __restrict__ s,
                                      const float* __restrict__ r,
                                      const float* __restrict__ t,
                                      const float* __restrict__ a,
                                      const float* __restrict__ ab,
                                      unsigned base, int m0) {
    loadCin(B, s, r, t, a, base, m0);
    loadCab(B, ab, base, m0);
}

// ---- compute helpers ----
__device__ __forceinline__ float compA(float rs_run, const BufA& B, int l0,
                                       float* sh, int tx) {
    #pragma unroll
    for (int k = 0; k < 4; ++k) {
        float dd = frcp(1.0f - rs_run * B.rv[k]);
        rs_run = B.rv[k] + rs_run * B.tv[k] * B.tv[k] * dd;
        sh[(l0 - k) * BLOCK + tx] = rs_run;
    }
    return rs_run;
}

// Phase B with FUSED reciprocal: one MUFU serves both ds and dt:
//   p = 1 - rs[l+1]*r[l]   (ds denominator)
//   q = 1 - rt[l-1]*r[l]   (dt denominator)
//   x = 1/(p*q);  ds = x*q;  dt = x*p;
__device__ __forceinline__ void compB(BState& st, const BufB& Bu, int l0,
                                      float* sh, int tx, unsigned base,
                                      float* fd, float* ab) {
    float rsv[4];
    #pragma unroll
    for (int k = 0; k < 4; ++k)
        rsv[k] = sh[(l0 + k + 1) * BLOCK + tx];   // rs[l+1]
    #pragma unroll
    for (int k = 0; k < 4; ++k) {
        unsigned idx = base + (unsigned)(l0 + k) * CCH;
        float s_down = st.ds_prev * (st.s_prev + Bu.sv[k] * st.r_prev);
        float G = st.F + s_down;
        __stcs(&fd[idx], G);

        float p = 1.0f - rsv[k] * Bu.rv[k];
        float q = 1.0f - st.rt_run * Bu.rv[k];
        float x = frcp(p * q);                      // single MUFU
        float dsl = x * q;                          // ds[l]
        float dtl = x * p;                          // dt[l]

        float td = Bu.tv[k] * dsl;
        ab[idx] = Bu.av[k] * (1.0f + rsv[k] * td) * G; // re-read in C
        st.F = G * td;
        st.ds_prev = dsl;

        st.rt_run = Bu.rv[k] + st.rt_run * Bu.tv[k] * Bu.tv[k] * dtl;
        sh[(l0 + k) * BLOCK + tx] = st.rt_run;         // overwrite dead rs

        st.s_prev = Bu.sv[k];
        st.r_prev = Bu.rv[k];
    }
}

// Phase C with pairwise-FUSED reciprocals: the 4 dt's in a batch are
// independent (rt from smem, r from gmem), so 2 MUFUs serve 4 dt's.
__device__ __forceinline__ void compC(CState& st, const BufC& Bu, int m0,
                                      float* sh, int tx, unsigned base,
                                      float* fu, float* ab) {
    float rtv[4], qv[4], dtv[4];
    #pragma unroll
    for (int k = 0; k < 4; ++k)
        rtv[k] = sh[(m0 - 2 - k) * BLOCK + tx];   // rt[m-2]
    #pragma unroll
    for (int k = 0; k < 4; ++k)
        qv[k] = 1.0f - rtv[k] * Bu.rv[k];
    {
        float x01 = frcp(qv[0] * qv[1]);
        float x23 = frcp(qv[2] * qv[3]);
        dtv[0] = x01 * qv[1];
        dtv[1] = x01 * qv[0];
        dtv[2] = x23 * qv[3];
        dtv[3] = x23 * qv[2];
    }
    #pragma unroll
    for (int k = 0; k < 4; ++k) {
        int mm = m0 - k;
        float dt_m1 = dtv[k];                           // dt[mm-1]
        float s_up = st.dt_m * (st.s_m + Bu.sv[k] * st.r_m);
        float G = st.Fu + s_up;
        __stcs(&fu[base + (unsigned)mm * CCH], G);

        float tdm1 = Bu.tv[k] * dt_m1;
        float au = G * Bu.av[k] * (1.0f + rtv[k] * tdm1);
        __stcs(&ab[base + (unsigned)(mm - 1) * CCH], Bu.abv[k] + au);
        st.Fu = G * tdm1;

        st.s_m = Bu.sv[k];
        st.r_m = Bu.rv[k];
        st.dt_m = dt_m1;
    }
}

__global__ __launch_bounds__(BLOCK, 5)   // 5 blocks/SM, reg cap 102
void adding_doubling_kernel(const float* __restrict__ a,
                            const float* __restrict__ r,
                            const float* __restrict__ t,
                            const float* __restrict__ s,
                            float* __restrict__ out)
{
    extern __shared__ float smem[];
    const int tx = threadIdx.x;

    const unsigned tid = blockIdx.x * BLOCK + tx;
    const unsigned base = (tid >> 7) * (NL * CCH) + (tid & (CCH - 1));
    const unsigned BNC  = BCOL * NL * CCH;

    float* fd = out;            // flux_down
    float* fu = out + BNC;      // flux_up
    float* ab = out + 2u * BNC; // absorbed

#define SH_R(l) smem[(l) * BLOCK + tx]

    BufB B0, B1;   // phase-B buffers (B0 pre-loaded during phase A tail)

    // ---------------- Phase A: bottom-up cumulative surface reflection ----
    // ROLLED pipeline: batches l0 = 58,54,...,6 (l=58..3), tail l=2,1
    {
        float rs_run = r[base + (NL - 1) * CCH];
        SH_R(NL - 1) = rs_run;

        BufA A0, A1;
        int l = NL - 2;                       // 58
        loadA(A0, r, t, base, l);
        #pragma unroll 1
        for (int it = 0; it < 6; ++it, l -= 8) {
            loadA(A1, r, t, base, l - 4);
            rs_run = compA(rs_run, A0, l, smem, tx);
            loadA(A0, r, t, base, l - 8);
            rs_run = compA(rs_run, A1, l - 4, smem, tx);
        }
        // l == 10; A0 holds batch 10
        loadA(A1, r, t, base, 6);
        rs_run = compA(rs_run, A0, 10, smem, tx);
        loadB(B0, s, r, t, a, base, 1);       // hide phase-B cold start
        rs_run = compA(rs_run, A1, 6, smem, tx);

        #pragma unroll
        for (int l2 = 2; l2 >= 1; --l2) {     // tail
            unsigned idx = base + (unsigned)l2 * CCH;
            float rl = r[idx], tl = t[idx];
            float dd = frcp(1.0f - rs_run * rl);
            rs_run = rl + rs_run * tl * tl * dd;
            SH_R(l2) = rs_run;
        }
    }

    BufC C0, C1;   // phase-C buffers (C0 inputs pre-loaded in phase B tail)

    // ---------------- Phase B: forward — down flux + top-down rt ----------
    // ROLLED pipeline: batches l0 = 1,5,...,53 (l=1..56), tail l=57..59
    {
        BState st;
        st.s_prev = s[base];
        st.r_prev = r[base];
        float rs1 = SH_R(1);
        st.ds_prev = frcp(1.0f - rs1 * st.r_prev);   // ds[0]
        st.rt_run = st.r_prev;                        // rt[0]
        SH_R(0) = st.rt_run;
        __stcs(&fd[base], 0.0f);
        st.F = 0.0f;

        int l = 1;
        #pragma unroll 1
        for (int it = 0; it < 6; ++it, l += 8) {
            loadB(B1, s, r, t, a, base, l + 4);
            compB(st, B0, l, smem, tx, base, fd, ab);
            loadB(B0, s, r, t, a, base, l + 8);
            compB(st, B1, l + 4, smem, tx, base, fd, ab);
        }
        // l == 49; B0 holds batch 49
        loadB(B1, s, r, t, a, base, 53);
        compB(st, B0, 49, smem, tx, base, fd, ab);
        loadCin(C0, s, r, t, a, base, 59);    // SAFE hoist: pure inputs only
        compB(st, B1, 53, smem, tx, base, fd, ab);

        #pragma unroll
        for (int l2 = 57; l2 < NL; ++l2) {    // tail l = 57, 58, 59
            unsigned idx = base + (unsigned)l2 * CCH;
            float sl = s[idx], rl = r[idx], tl = t[idx], al = a[idx];

            float s_down = st.ds_prev * (st.s_prev + sl * st.r_prev);
            float G = st.F + s_down;
            __stcs(&fd[idx], G);

            float absd;
            if (l2 < NL - 1) {
                float rsl1 = SH_R(l2 + 1);
                float dsl  = frcp(1.0f - rsl1 * rl);
                float td = tl * dsl;
                absd = al * (1.0f + rsl1 * td) * G;
                st.F = G * td;
                st.ds_prev = dsl;
            } else {
                absd = al * G;
            }
            ab[idx] = absd;

            float dd = frcp(1.0f - st.rt_run * rl);
            st.rt_run = rl + st.rt_run * tl * tl * dd;
            SH_R(l2) = st.rt_run;

            st.s_prev = sl;
            st.r_prev = rl;
        }
    }

    // ---------------- Phase C: reverse — up flux ---------------------------
    // ROLLED pipeline: batches m0 = 59,55,...,7 (m=59..4), tail m=3,2, epi.
    {
        // ab[55..58] were written by this same thread in phase B above;
        // load here (after the writes) — program-order correct, L1/L2 hit.
        loadCab(C0, ab, base, 59);

        CState st;
        st.Fu = 0.0f;
        unsigned idxN = base + (NL - 1) * CCH;
        st.s_m = __ldcs(&s[idxN]);
        st.r_m = __ldcs(&r[idxN]);
        st.dt_m = frcp(1.0f - SH_R(NL - 2) * st.r_m);   // dt[N-1]

        int m = NL - 1;                        // 59
        #pragma unroll 1
        for (int it = 0; it < 6; ++it, m -= 8) {
            loadC(C1, s, r, t, a, ab, base, m - 4);
            compC(st, C0, m, smem, tx, base, fu, ab);
            loadC(C0, s, r, t, a, ab, base, m - 8);
            compC(st, C1, m - 4, smem, tx, base, fu, ab);
        }
        // m == 11; C0 holds batch 11
        loadC(C1, s, r, t, a, ab, base, 7);
        compC(st, C0, 11, smem, tx, base, fu, ab);
        compC(st, C1, 7, smem, tx, base, fu, ab);

        #pragma unroll
        for (int m2 = 3; m2 >= 2; --m2) {      // tail m = 3, 2
            unsigned idxm1 = base + (unsigned)(m2 - 1) * CCH;
            float s_m1 = __ldcs(&s[idxm1]);
            float r_m1 = __ldcs(&r[idxm1]);
            float t_m1 = __ldcs(&t[idxm1]);
            float a_m1 = __ldcs(&a[idxm1]);
            float ab_old = __ldcs(&ab[idxm1]);

            float rt_m2 = SH_R(m2 - 2);
            float dt_m1 = frcp(1.0f - rt_m2 * r_m1);

            float s_up_m = st.dt_m * (st.s_m + s_m1 * st.r_m);
            float G = st.Fu + s_up_m;
            __stcs(&fu[base + (unsigned)m2 * CCH], G);

            float tdm1 = t_m1 * dt_m1;
            float au = G * a_m1 * (1.0f + rt_m2 * tdm1);
            __stcs(&ab[idxm1], ab_old + au);
            st.Fu = G * tdm1;

            st.s_m = s_m1;
            st.r_m = r_m1;
            st.dt_m = dt_m1;
        }

        // m = 1 and m = 0 epilogue; state: s_m=s[1], r_m=r[1], dt_m=dt[1]
        float s0 = __ldcs(&s[base]);
        float t0 = __ldcs(&t[base]);
        float a0 = __ldcs(&a[base]);
        float s_up1 = st.dt_m * (st.s_m + s0 * st.r_m);
        float flux1 = st.Fu + s_up1;
        __stcs(&fu[base + CCH], flux1);           // flux_up[1]
        __stcs(&ab[base], flux1 * a0);            // absorbed[0] (down = 0)
        __stcs(&fu[base], flux1 * t0 + s0);       // flux_up[0]
    }

#undef SH_R
}

extern "C" void kernel_launch(void* const* d_in, const int* in_sizes, int n_in,
                              void* d_out, int out_size)
{
    const float* a = (const float*)d_in[0];
    const float* r = (const float*)d_in[1];
    const float* t = (const float*)d_in[2];
    const float* s = (const float*)d_in[3];
    float* out = (float*)d_out;

    cudaFuncSetAttribute(adding_doubling_kernel,
                         cudaFuncAttributeMaxDynamicSharedMemorySize,
                         (int)SMEM_BYTES);

    const int total = BCOL * CCH;                 // 262144 threads
    const int grid = (total + BLOCK - 1) / BLOCK; // 2048 blocks
    adding_doubling_kernel<<<grid, BLOCK, SMEM_BYTES>>>(a, r, t, s, out);
}